// round 1
// baseline (speedup 1.0000x reference)
#include <cuda_runtime.h>
#include <cuda_bf16.h>

// C = tril(tril(A) @ tril(B)), N=4096, fp32.
// C[i,j] = sum_{k=j..i} A[i,k]*B[k,j] for i>=j, else 0.
//
// Strategy: 128x128 block tiles over (i,j). Blocks strictly above the
// diagonal write zeros. Lower blocks loop k only over [bj*128, (bi+1)*128)
// (the only range that can contribute), with tril masks applied when
// staging tiles into shared memory. Inner loop is a dense 8x8 FMA microtile.

#define NDIM 4096
#define BM 128
#define BN 128
#define BK 8
#define NTHREADS 256

__global__ __launch_bounds__(NTHREADS, 2)
void trilmm_kernel(const float* __restrict__ A,
                   const float* __restrict__ B,
                   float* __restrict__ C) {
    const int bj = blockIdx.x;          // column tile
    const int bi = blockIdx.y;          // row tile
    const int jBase = bj * BN;
    const int iBase = bi * BM;
    const int tid = threadIdx.x;

    // Strictly-upper block: write zeros, done.
    if (bi < bj) {
        const float4 z = make_float4(0.f, 0.f, 0.f, 0.f);
        // 128*128/4 = 4096 float4 stores, 16 per thread
        #pragma unroll
        for (int it = 0; it < (BM * BN / 4) / NTHREADS; it++) {
            int idx = it * NTHREADS + tid;           // 0..4095
            int r = idx >> 5;                        // 0..127
            int c = (idx & 31) << 2;                 // 0..124
            *reinterpret_cast<float4*>(&C[(iBase + r) * NDIM + jBase + c]) = z;
        }
        return;
    }

    __shared__ float As[BK][BM];   // transposed: As[k][i]
    __shared__ float Bs[BK][BN];   // Bs[k][j]

    float acc[8][8];
    #pragma unroll
    for (int m = 0; m < 8; m++)
        #pragma unroll
        for (int n = 0; n < 8; n++)
            acc[m][n] = 0.f;

    const int tx = tid & 15;       // 0..15 -> columns tx*8..tx*8+7
    const int ty = tid >> 4;       // 0..15 -> rows    ty*8..ty*8+7

    // A-tile load mapping: 128 rows x 8 k, float4 along k -> 256 loads
    const int aRow = tid >> 1;              // 0..127
    const int aK   = (tid & 1) << 2;        // 0 or 4
    // B-tile load mapping: 8 k x 128 cols, float4 along j -> 256 loads
    const int bK   = tid >> 5;              // 0..7
    const int bCol = (tid & 31) << 2;       // 0..124

    const int gi_a = iBase + aRow;          // global row for A load
    const int kStart = jBase;               // min useful k = min j in tile
    const int kEnd   = iBase + BM;          // max useful k = max i in tile + 1

    for (int k0 = kStart; k0 < kEnd; k0 += BK) {
        // ---- stage A (mask: A[i,k] live iff k <= i) ----
        float4 av = *reinterpret_cast<const float4*>(&A[gi_a * NDIM + k0 + aK]);
        As[aK + 0][aRow] = (k0 + aK + 0 <= gi_a) ? av.x : 0.f;
        As[aK + 1][aRow] = (k0 + aK + 1 <= gi_a) ? av.y : 0.f;
        As[aK + 2][aRow] = (k0 + aK + 2 <= gi_a) ? av.z : 0.f;
        As[aK + 3][aRow] = (k0 + aK + 3 <= gi_a) ? av.w : 0.f;

        // ---- stage B (mask: B[k,j] live iff k >= j) ----
        const int gk = k0 + bK;
        const int gj = jBase + bCol;
        float4 bv = *reinterpret_cast<const float4*>(&B[gk * NDIM + gj]);
        float4 bm;
        bm.x = (gk >= gj + 0) ? bv.x : 0.f;
        bm.y = (gk >= gj + 1) ? bv.y : 0.f;
        bm.z = (gk >= gj + 2) ? bv.z : 0.f;
        bm.w = (gk >= gj + 3) ? bv.w : 0.f;
        *reinterpret_cast<float4*>(&Bs[bK][bCol]) = bm;

        __syncthreads();

        #pragma unroll
        for (int kk = 0; kk < BK; kk++) {
            float4 a0 = *reinterpret_cast<const float4*>(&As[kk][ty * 8]);
            float4 a1 = *reinterpret_cast<const float4*>(&As[kk][ty * 8 + 4]);
            float4 b0 = *reinterpret_cast<const float4*>(&Bs[kk][tx * 8]);
            float4 b1 = *reinterpret_cast<const float4*>(&Bs[kk][tx * 8 + 4]);
            float a[8] = {a0.x, a0.y, a0.z, a0.w, a1.x, a1.y, a1.z, a1.w};
            float b[8] = {b0.x, b0.y, b0.z, b0.w, b1.x, b1.y, b1.z, b1.w};
            #pragma unroll
            for (int m = 0; m < 8; m++)
                #pragma unroll
                for (int n = 0; n < 8; n++)
                    acc[m][n] = fmaf(a[m], b[n], acc[m][n]);
        }

        __syncthreads();
    }

    // ---- epilogue: C[i,j] = (i >= j) ? acc : 0 ----
    #pragma unroll
    for (int m = 0; m < 8; m++) {
        const int gi = iBase + ty * 8 + m;
        #pragma unroll
        for (int n = 0; n < 8; n += 4) {
            const int gj = jBase + tx * 8 + n;
            float4 v;
            v.x = (gi >= gj + 0) ? acc[m][n + 0] : 0.f;
            v.y = (gi >= gj + 1) ? acc[m][n + 1] : 0.f;
            v.z = (gi >= gj + 2) ? acc[m][n + 2] : 0.f;
            v.w = (gi >= gj + 3) ? acc[m][n + 3] : 0.f;
            *reinterpret_cast<float4*>(&C[gi * NDIM + gj]) = v;
        }
    }
}

extern "C" void kernel_launch(void* const* d_in, const int* in_sizes, int n_in,
                              void* d_out, int out_size) {
    const float* A = (const float*)d_in[0];
    const float* B = (const float*)d_in[1];
    float* C = (float*)d_out;
    (void)in_sizes; (void)n_in; (void)out_size;

    dim3 grid(NDIM / BN, NDIM / BM);   // (32, 32)
    dim3 block(NTHREADS);
    trilmm_kernel<<<grid, block>>>(A, B, C);
}

// round 3
// speedup vs baseline: 1.5497x; 1.5497x over previous
#include <cuda_runtime.h>
#include <cstdint>

// C = tril(tril(A) @ tril(B)), N=4096, fp32.
// TF32 mma.sync.m16n8k8 tensor-core GEMM with triangular block skipping.
// 128x128 tiles, BK=32 chunks, K in [bj*128, (bi+1)*128).
// SMEM holds tiles pre-permuted into mma fragment layout; double-buffered,
// register-staged loads overlap LDG with MMA.

#define NDIM 4096
#define BM 128
#define BN 128
#define BK 32
#define NTHREADS 256

// SMEM: A0[0,16K) B0[16K,32K) A1[32K,48K) B1[48K,64K)
#define SMEM_TOTAL 65536

extern __shared__ char smem[];

__device__ __forceinline__ uint32_t smem_u32(const void* p) {
    uint32_t a;
    asm("{ .reg .u64 t; cvta.to.shared.u64 t, %1; cvt.u32.u64 %0, t; }" : "=r"(a) : "l"(p));
    return a;
}

__device__ __forceinline__ uint32_t tf32r(float x) {
    uint32_t u;
    asm("cvt.rna.tf32.f32 %0, %1;" : "=r"(u) : "f"(x));
    return u;
}

__device__ __forceinline__ void mma8(float* d, const uint32_t* a, const uint32_t* b) {
    asm volatile(
        "mma.sync.aligned.m16n8k8.row.col.f32.tf32.tf32.f32 "
        "{%0,%1,%2,%3}, {%4,%5,%6,%7}, {%8,%9}, {%0,%1,%2,%3};"
        : "+f"(d[0]), "+f"(d[1]), "+f"(d[2]), "+f"(d[3])
        : "r"(a[0]), "r"(a[1]), "r"(a[2]), "r"(a[3]), "r"(b[0]), "r"(b[1]));
}

__global__ __launch_bounds__(NTHREADS, 1)
void trilmm_mma(const float* __restrict__ A,
                const float* __restrict__ B,
                float* __restrict__ C) {
    const int id = blockIdx.x;
    const int tid = threadIdx.x;

    int bi, bj;
    if (id < 528) {
        // lower-triangular tiles, heaviest diagonal distance first
        int d = 31, cum = 0, t = id;
        while (cum + (32 - d) <= t) { cum += 32 - d; d--; }
        bj = t - cum;
        bi = d + bj;
    } else {
        // strictly-upper tiles: zero-fill and exit
        int uid = id - 528;
        int r = 0, cum = 0;
        while (cum + (31 - r) <= uid) { cum += 31 - r; r++; }
        bi = r;
        bj = r + 1 + (uid - cum);
        const int iBase = bi * BM, jBase = bj * BN;
        const float4 z = make_float4(0.f, 0.f, 0.f, 0.f);
        #pragma unroll
        for (int it = 0; it < (BM * BN / 4) / NTHREADS; it++) {
            int idx = it * NTHREADS + tid;
            int rr = idx >> 5;
            int cc = (idx & 31) << 2;
            *reinterpret_cast<float4*>(&C[(iBase + rr) * NDIM + jBase + cc]) = z;
        }
        return;
    }

    const int iBase = bi * BM;
    const int jBase = bj * BN;
    const int wid = tid >> 5;
    const int lane = tid & 31;
    const int wm = wid & 1;        // warp m index (0..1), 64 rows each
    const int wn = wid >> 1;       // warp n index (0..3), 32 cols each

    const uint32_t sbase = smem_u32(smem);
    const uint32_t aBuf[2] = {sbase + 0u,     sbase + 32768u};
    const uint32_t bBuf[2] = {sbase + 16384u, sbase + 49152u};

    float acc[4][4][4];   // [mt][nt][frag]
    #pragma unroll
    for (int m = 0; m < 4; m++)
        #pragma unroll
        for (int n = 0; n < 4; n++)
            #pragma unroll
            for (int f = 0; f < 4; f++)
                acc[m][n][f] = 0.f;

    const int nChunks = (bi - bj + 1) * (BM / BK);
    const int kStart = jBase;

    // staging index precompute
    const int aR  = tid >> 1;               // reused per-iter below instead
    (void)aR;

    float4 aReg[4], bReg[4];

    // ---- load chunk 0 into registers ----
    {
        const int k0 = kStart;
        #pragma unroll
        for (int it = 0; it < 4; it++) {
            int idx = it * NTHREADS + tid;
            int r  = idx >> 3;            // 0..127
            int c4 = idx & 7;             // k offset c4*4
            aReg[it] = *reinterpret_cast<const float4*>(&A[(iBase + r) * NDIM + k0 + c4 * 4]);
            int kB = idx >> 5;            // 0..31
            int n4 = idx & 31;
            bReg[it] = *reinterpret_cast<const float4*>(&B[(k0 + kB) * NDIM + jBase + n4 * 4]);
        }
    }

    for (int c = 0; c < nChunks; c++) {
        const int b = c & 1;
        const int k0s = kStart + c * BK;

        // ---- store staged registers into fragment-layout SMEM (with masks + tf32) ----
        #pragma unroll
        for (int it = 0; it < 4; it++) {
            int idx = it * NTHREADS + tid;
            // A: element (r, kk=c4*4+e) -> block (mt*4+ks), lane2, slot
            {
                int r  = idx >> 3;
                int c4 = idx & 7;
                int gi = iBase + r;
                int mt = r >> 4;
                int rr = r & 15;
                int ks = c4 >> 1;
                int slot = (rr >> 3) + ((c4 & 1) << 1);
                int lane2base = (rr & 7) << 2;
                uint32_t addr0 = aBuf[b] + ((((mt << 2) + ks) << 5) + lane2base) * 16 + (slot << 2);
                const float* av = reinterpret_cast<const float*>(&aReg[it]);
                #pragma unroll
                for (int e = 0; e < 4; e++) {
                    uint32_t v = (k0s + c4 * 4 + e <= gi) ? tf32r(av[e]) : 0u;
                    asm volatile("st.shared.b32 [%0], %1;" :: "r"(addr0 + e * 16), "r"(v) : "memory");
                }
            }
            // B: element (kB, n=n4*4+e) -> block (nt*4+ks), lane2, slot
            {
                int kB = idx >> 5;
                int n4 = idx & 31;
                int gk = k0s + kB;
                int nt = n4 >> 1;
                int ks = kB >> 3;
                int slot = (kB >> 2) & 1;
                int kk3 = kB & 3;
                const float* bv = reinterpret_cast<const float*>(&bReg[it]);
                #pragma unroll
                for (int e = 0; e < 4; e++) {
                    int nn = ((n4 & 1) << 2) + e;          // n within 8-col tile
                    int lane2 = (nn << 2) + kk3;
                    uint32_t addr = bBuf[b] + ((((nt << 2) + ks) << 5) + lane2) * 8 + (slot << 2);
                    uint32_t v = (gk >= jBase + n4 * 4 + e) ? tf32r(bv[e]) : 0u;
                    asm volatile("st.shared.b32 [%0], %1;" :: "r"(addr), "r"(v) : "memory");
                }
            }
        }

        __syncthreads();

        // ---- issue LDG for next chunk (overlaps with MMA below) ----
        if (c + 1 < nChunks) {
            const int k0 = kStart + (c + 1) * BK;
            #pragma unroll
            for (int it = 0; it < 4; it++) {
                int idx = it * NTHREADS + tid;
                int r  = idx >> 3;
                int c4 = idx & 7;
                aReg[it] = *reinterpret_cast<const float4*>(&A[(iBase + r) * NDIM + k0 + c4 * 4]);
                int kB = idx >> 5;
                int n4 = idx & 31;
                bReg[it] = *reinterpret_cast<const float4*>(&B[(k0 + kB) * NDIM + jBase + n4 * 4]);
            }
        }

        // ---- compute: 4 k-steps x (4 mt x 4 nt) m16n8k8 ----
        #pragma unroll
        for (int ks = 0; ks < 4; ks++) {
            uint32_t af[4][4];
            #pragma unroll
            for (int mt = 0; mt < 4; mt++) {
                uint32_t addr = aBuf[b] + (((((wm << 2) + mt) << 2) + ks) << 5 | lane) * 16;
                asm volatile("ld.shared.v4.b32 {%0,%1,%2,%3}, [%4];"
                             : "=r"(af[mt][0]), "=r"(af[mt][1]), "=r"(af[mt][2]), "=r"(af[mt][3])
                             : "r"(addr));
            }
            uint32_t bf[4][2];
            #pragma unroll
            for (int nt = 0; nt < 4; nt++) {
                uint32_t addr = bBuf[b] + (((((wn << 2) + nt) << 2) + ks) << 5 | lane) * 8;
                asm volatile("ld.shared.v2.b32 {%0,%1}, [%2];"
                             : "=r"(bf[nt][0]), "=r"(bf[nt][1])
                             : "r"(addr));
            }
            #pragma unroll
            for (int mt = 0; mt < 4; mt++)
                #pragma unroll
                for (int nt = 0; nt < 4; nt++)
                    mma8(acc[mt][nt], af[mt], bf[nt]);
        }

        __syncthreads();
    }

    // ---- epilogue: fragments -> C with tril mask ----
    const int gID = lane >> 2;        // 0..7
    const int tig = lane & 3;         // 0..3
    #pragma unroll
    for (int mt = 0; mt < 4; mt++) {
        #pragma unroll
        for (int nt = 0; nt < 4; nt++) {
            const int gi0 = iBase + wm * 64 + mt * 16 + gID;
            const int gj0 = jBase + wn * 32 + nt * 8 + tig * 2;
            float2 v0;
            v0.x = (gi0 >= gj0)     ? acc[mt][nt][0] : 0.f;
            v0.y = (gi0 >= gj0 + 1) ? acc[mt][nt][1] : 0.f;
            *reinterpret_cast<float2*>(&C[gi0 * NDIM + gj0]) = v0;
            const int gi1 = gi0 + 8;
            float2 v1;
            v1.x = (gi1 >= gj0)     ? acc[mt][nt][2] : 0.f;
            v1.y = (gi1 >= gj0 + 1) ? acc[mt][nt][3] : 0.f;
            *reinterpret_cast<float2*>(&C[gi1 * NDIM + gj0]) = v1;
        }
    }
}

extern "C" void kernel_launch(void* const* d_in, const int* in_sizes, int n_in,
                              void* d_out, int out_size) {
    const float* A = (const float*)d_in[0];
    const float* B = (const float*)d_in[1];
    float* C = (float*)d_out;
    (void)in_sizes; (void)n_in; (void)out_size;

    cudaFuncSetAttribute(trilmm_mma, cudaFuncAttributeMaxDynamicSharedMemorySize, SMEM_TOTAL);
    trilmm_mma<<<1024, NTHREADS, SMEM_TOTAL>>>(A, B, C);
}

// round 5
// speedup vs baseline: 5.0890x; 3.2838x over previous
#include <cuda_runtime.h>
#include <cstdint>

// C = tril(tril(A) @ tril(B)), N=4096, fp32.
// TF32 m16n8k8 mma.sync; 256x128 block tiles, 64x64 warp tiles (8 warps, 4x2).
// cp.async.cg direct global->SMEM (canonical layout), 4-stage pipeline.
// tf32 via HW truncation of fp32 bits. Triangular masks via in-SMEM zero
// passes on edge chunks only. Strictly-upper 256x128 tiles zero-fill.

#define NN 4096
#define BM 256
#define BN 128
#define BK 32
#define STAGES 4
#define BROW 544                      // padded B row: 128 floats + 8 pad (bytes)
#define A_STAGE (BM * BK * 4)         // 32768
#define B_STAGE (BK * BROW)           // 17408
#define STAGE_BYTES (A_STAGE + B_STAGE)
#define B_OFF A_STAGE
#define SMEM_TOTAL (STAGES * STAGE_BYTES)   // 200704
#define N_LOWER 272

extern __shared__ char smem[];

__device__ __forceinline__ uint32_t smem_u32(const void* p) {
    uint32_t a;
    asm("{ .reg .u64 t; cvta.to.shared.u64 t, %1; cvt.u32.u64 %0, t; }" : "=r"(a) : "l"(p));
    return a;
}

__device__ __forceinline__ void cp16(uint32_t dst, const void* src) {
    asm volatile("cp.async.cg.shared.global [%0], [%1], 16;" :: "r"(dst), "l"(src) : "memory");
}

__device__ __forceinline__ uint32_t lds32(uint32_t a) {
    uint32_t v;
    asm volatile("ld.shared.b32 %0, [%1];" : "=r"(v) : "r"(a));
    return v;
}

__device__ __forceinline__ void sts32(uint32_t a, uint32_t v) {
    asm volatile("st.shared.b32 [%0], %1;" :: "r"(a), "r"(v) : "memory");
}

__device__ __forceinline__ void mma8(float* d, const uint32_t* a, const uint32_t* b) {
    asm volatile(
        "mma.sync.aligned.m16n8k8.row.col.f32.tf32.tf32.f32 "
        "{%0,%1,%2,%3}, {%4,%5,%6,%7}, {%8,%9}, {%0,%1,%2,%3};"
        : "+f"(d[0]), "+f"(d[1]), "+f"(d[2]), "+f"(d[3])
        : "r"(a[0]), "r"(a[1]), "r"(a[2]), "r"(a[3]), "r"(b[0]), "r"(b[1]));
}

__global__ __launch_bounds__(256, 1)
void trilmm4(const float* __restrict__ A,
             const float* __restrict__ B,
             float* __restrict__ C) {
    const int id = blockIdx.x;
    const int tid = threadIdx.x;

    int bi = 0, bj = 0;
    if (id >= N_LOWER) {
        // strictly-upper 256x128 tile: zero-fill, exit
        int uid = id - N_LOWER;
        int b2 = 0;
        #pragma unroll 1
        while (uid >= 30 - 2 * b2) { uid -= 30 - 2 * b2; b2++; }
        bi = b2;
        bj = 2 * b2 + 2 + uid;
        const int iB = bi * BM, jB = bj * BN;
        const float4 z = make_float4(0.f, 0.f, 0.f, 0.f);
        // 256 rows x 128 cols = 8192 float4 = 32 iterations of 256 threads
        #pragma unroll 4
        for (int it = 0; it < 32; it++) {
            int idx = it * 256 + tid;
            int r = idx >> 5;               // 0..255
            int c = (idx & 31) << 2;        // 0..124
            *reinterpret_cast<float4*>(&C[(iB + r) * NN + jB + c]) = z;
        }
        return;
    }

    // lower tiles, heaviest (largest k-range) first: d = 2*bi - bj from 30 down to -1
    {
        int rem = id;
        #pragma unroll 1
        for (int d = 30; d >= -1; d--) {
            int lo = (d + 1) >> 1;
            if (lo < 0) lo = 0;
            int hi = (d + 31) >> 1; if (hi > 15) hi = 15;
            int cnt = hi - lo + 1;
            if (rem < cnt) { bi = lo + rem; bj = 2 * bi - d; break; }
            rem -= cnt;
        }
    }

    const int iBase = bi * BM;
    const int jBase = bj * BN;
    const int wid = tid >> 5;
    const int lane = tid & 31;
    const int g  = lane >> 2;      // 0..7
    const int kt = lane & 3;       // 0..3
    const int mbase = (wid & 3) * 64;
    const int nbase = (wid >> 2) * 64;

    const uint32_t sbase = smem_u32(smem);
    const uint32_t xg = (uint32_t)g << 4;

    // per-thread relative offsets for fragment loads
    uint32_t rowrel[4], brel[8];
    #pragma unroll
    for (int mt = 0; mt < 4; mt++) rowrel[mt] = (uint32_t)(mbase + mt * 16 + g) * 128u;
    #pragma unroll
    for (int nt = 0; nt < 8; nt++) brel[nt] = (uint32_t)(nbase + nt * 8 + g) * 4u;

    float acc[4][8][4];
    #pragma unroll
    for (int mt = 0; mt < 4; mt++)
        #pragma unroll
        for (int nt = 0; nt < 8; nt++)
            #pragma unroll
            for (int f = 0; f < 4; f++)
                acc[mt][nt][f] = 0.f;

    const int kStart = jBase;
    const int nCh = (iBase + BM - jBase) / BK;    // >= 4

    // ---- cp.async issue for chunk c (always commits a group) ----
    auto issue = [&](int c) {
        if (c < nCh) {
            const int k0 = kStart + c * BK;
            const uint32_t sb = sbase + (uint32_t)(c % STAGES) * STAGE_BYTES;
            #pragma unroll
            for (int it = 0; it < 8; it++) {       // A: 256 rows x 128B
                int idx = it * 256 + tid;
                int r = idx >> 3, g8 = idx & 7;
                const float* src = &A[(iBase + r) * NN + k0 + g8 * 4];
                uint32_t kb = (uint32_t)(g8 * 16);
                cp16(sb + (uint32_t)r * 128u + (kb ^ ((uint32_t)(r & 7) << 4)), src);
            }
            #pragma unroll
            for (int it = 0; it < 4; it++) {       // B: 32 rows x 512B (pad 544)
                int idx = it * 256 + tid;
                int kk = idx >> 5, n16 = idx & 31;
                const float* src = &B[(k0 + kk) * NN + jBase + n16 * 4];
                cp16(sb + B_OFF + (uint32_t)kk * BROW + (uint32_t)n16 * 16u, src);
            }
        }
        asm volatile("cp.async.commit_group;" ::: "memory");
    };

    issue(0); issue(1); issue(2);

    for (int c = 0; c < nCh; c++) {
        asm volatile("cp.async.wait_group 2;" ::: "memory");
        __syncthreads();

        issue(c + 3);

        const int k0 = kStart + c * BK;
        const uint32_t sA = sbase + (uint32_t)(c % STAGES) * STAGE_BYTES;
        const uint32_t sB = sA + B_OFF;

        // ---- edge masking: zero forbidden entries in SMEM ----
        const bool aEdge = (k0 >= iBase);
        const bool bEdge = (k0 < jBase + BN);
        if (aEdge) {
            const int off = k0 - iBase;            // zero A[r][kk] iff kk > r - off
            #pragma unroll 4
            for (int it = 0; it < 32; it++) {
                int idx = it * 256 + tid;
                int r = idx >> 5, kk = idx & 31;
                if (kk > r - off)
                    sts32(sA + (uint32_t)r * 128u +
                          (((uint32_t)kk * 4u) ^ ((uint32_t)(r & 7) << 4)), 0u);
            }
        }
        if (bEdge) {
            const int offb = k0 - jBase;           // zero B[kk][n] iff n > offb + kk
            #pragma unroll 4
            for (int it = 0; it < 16; it++) {
                int idx = it * 256 + tid;
                int n = idx & 127, kk = idx >> 7;
                if (n > offb + kk)
                    sts32(sB + (uint32_t)kk * BROW + (uint32_t)n * 4u, 0u);
            }
        }
        if (aEdge || bEdge) __syncthreads();

        // ---- compute: 4 k-steps, 32 MMAs each ----
        #pragma unroll
        for (int ks = 0; ks < 4; ks++) {
            const uint32_t kb0 = (uint32_t)(ks * 32 + kt * 4);
            uint32_t af[4][4];
            #pragma unroll
            for (int mt = 0; mt < 4; mt++) {
                uint32_t a0 = sA + rowrel[mt] + (kb0 ^ xg);
                uint32_t a2 = sA + rowrel[mt] + ((kb0 + 16u) ^ xg);
                af[mt][0] = lds32(a0);
                af[mt][1] = lds32(a0 + 1024u);
                af[mt][2] = lds32(a2);
                af[mt][3] = lds32(a2 + 1024u);
            }
            uint32_t bf[8][2];
            const uint32_t bk0 = (uint32_t)(ks * 8 + kt) * BROW;
            #pragma unroll
            for (int nt = 0; nt < 8; nt++) {
                uint32_t b0 = sB + bk0 + brel[nt];
                bf[nt][0] = lds32(b0);
                bf[nt][1] = lds32(b0 + 4u * BROW);
            }
            #pragma unroll
            for (int mt = 0; mt < 4; mt++)
                #pragma unroll
                for (int nt = 0; nt < 8; nt++)
                    mma8(acc[mt][nt], af[mt], bf[nt]);
        }
    }

    // ---- epilogue: tril-masked float2 stores ----
    const int tig = lane & 3;
    #pragma unroll
    for (int mt = 0; mt < 4; mt++) {
        #pragma unroll
        for (int nt = 0; nt < 8; nt++) {
            const int gi0 = iBase + mbase + mt * 16 + g;
            const int gj0 = jBase + nbase + nt * 8 + tig * 2;
            float2 v0;
            v0.x = (gi0 >= gj0)     ? acc[mt][nt][0] : 0.f;
            v0.y = (gi0 >= gj0 + 1) ? acc[mt][nt][1] : 0.f;
            *reinterpret_cast<float2*>(&C[gi0 * NN + gj0]) = v0;
            const int gi1 = gi0 + 8;
            float2 v1;
            v1.x = (gi1 >= gj0)     ? acc[mt][nt][2] : 0.f;
            v1.y = (gi1 >= gj0 + 1) ? acc[mt][nt][3] : 0.f;
            *reinterpret_cast<float2*>(&C[gi1 * NN + gj0]) = v1;
        }
    }
}

extern "C" void kernel_launch(void* const* d_in, const int* in_sizes, int n_in,
                              void* d_out, int out_size) {
    const float* A = (const float*)d_in[0];
    const float* B = (const float*)d_in[1];
    float* C = (float*)d_out;
    (void)in_sizes; (void)n_in; (void)out_size;

    cudaFuncSetAttribute(trilmm4, cudaFuncAttributeMaxDynamicSharedMemorySize, SMEM_TOTAL);
    trilmm4<<<512, 256, SMEM_TOTAL>>>(A, B, C);
}